// round 11
// baseline (speedup 1.0000x reference)
#include <cuda_runtime.h>
#include <math.h>

#define Bn 2048
#define DXc 256
#define DZc 64
#define CQ 80
#define INV_B (1.0f/2048.0f)
#define NBLK 148
#define NTH 512
#define NJ 8
#define NI 8

// ------------- device scratch -------------
__device__ float g_K0 [Bn*(size_t)Bn];
__device__ float g_K0T[Bn*(size_t)Bn];
__device__ float g_Zb [Bn*CQ];
__device__ float g_Y  [Bn*CQ];
__device__ float g_Yp [NJ*Bn*CQ];
__device__ float g_Pp [NI*DXc*CQ];
__device__ float g_csp[NI][CQ], g_asp[NI][CQ];
__device__ float g_A  [Bn*CQ];
__device__ float g_rsp[32][Bn];
__device__ float g_u[Bn], g_v[Bn];
__device__ float g_ax[Bn], g_az[Bn];
__device__ float g_cx[Bn], g_cz[Bn];
__device__ float g_rowsqx[Bn], g_rowsqz[Bn];
__device__ float g_p[Bn], g_q[Bn], g_m[Bn];
__device__ float g_xs[DXc], g_zs[DZc];
__device__ float g_sax, g_saz;
__device__ double g_sumCx, g_sumCz, g_reg, g_cross;
__device__ float g_sx, g_sz, g_mCx2, g_mCz2;
__device__ int g_barCount, g_barSense;

// shared-memory union for the fused iteration kernel
struct SA { float Ks[16][136]; float Bs[16][80]; float vsh[256]; };
struct SB { float Xs[16][16]; float Ms[16][80]; float axsh[16]; };
struct SC { float Xt[16][136]; float Ps[16][16]; float csRs[16]; float asRs[16]; };
struct SD { float At[64][72]; float Zt[64][68]; float a0s[64], a1s[64], cxs[64], azs[64], czs[64]; };
struct SE { float vs[Bn]; float red[4][4]; };
union SMU { SA a; SB b; SC c; SD d; SE e; };

// ------------- helpers -------------
__device__ __forceinline__ float blockReduce256(float v, float* sh, int t) {
    #pragma unroll
    for (int o = 16; o; o >>= 1) v += __shfl_down_sync(0xffffffffu, v, o);
    if ((t & 31) == 0) sh[t >> 5] = v;
    __syncthreads();
    if (t < 32) {
        v = (t < 8) ? sh[t] : 0.0f;
        #pragma unroll
        for (int o = 4; o; o >>= 1) v += __shfl_down_sync(0xffffffffu, v, o);
    }
    __syncthreads();
    return v;
}

// ------------- prologue -------------
__global__ void k_init() {
    int t = blockIdx.x * blockDim.x + threadIdx.x;
    if (t == 0) { g_sumCx = 0.0; g_sumCz = 0.0; g_reg = 0.0; g_cross = 0.0;
                  g_sax = 0.0f; g_saz = 0.0f; }
    if (t < Bn) { g_rowsqx[t] = 0.0f; g_rowsqz[t] = 0.0f; }
    if (t < DXc) g_xs[t] = 0.0f;
    if (t < DZc) g_zs[t] = 0.0f;
}

__global__ void k_sqnorm(const float* __restrict__ X, int D, int which) {
    __shared__ float sh[8];
    int i = blockIdx.x;
    float s = 0.0f;
    for (int k = threadIdx.x; k < D; k += 256) { float x = X[i * D + k]; s += x * x; }
    s = blockReduce256(s, sh, threadIdx.x);
    if (threadIdx.x == 0) { if (which == 0) g_ax[i] = s; else g_az[i] = s; }
}

__global__ void k_stats(const float* __restrict__ X, int D, int which) {
    __shared__ float Xa[64][17];
    __shared__ float Xb[64][17];
    __shared__ float rowacc[64];
    __shared__ float sh[8];
    int tx = threadIdx.x, ty = threadIdx.y;
    int t = ty * 16 + tx;
    int i0 = blockIdx.y * 64, j0 = blockIdx.x * 64;
    float acc[4][4];
    #pragma unroll
    for (int r = 0; r < 4; r++)
        #pragma unroll
        for (int c = 0; c < 4; c++) acc[r][c] = 0.0f;
    for (int k0 = 0; k0 < D; k0 += 16) {
        #pragma unroll
        for (int e = 0; e < 4; e++) {
            int idx = t + e * 256;
            int r = idx >> 4, kk = idx & 15;
            Xa[r][kk] = X[(i0 + r) * D + k0 + kk];
            Xb[r][kk] = X[(j0 + r) * D + k0 + kk];
        }
        __syncthreads();
        #pragma unroll
        for (int kk = 0; kk < 16; kk++) {
            float fa[4], fb[4];
            #pragma unroll
            for (int r = 0; r < 4; r++) fa[r] = Xa[ty * 4 + r][kk];
            #pragma unroll
            for (int c = 0; c < 4; c++) fb[c] = Xb[tx * 4 + c][kk];
            #pragma unroll
            for (int r = 0; r < 4; r++)
                #pragma unroll
                for (int c = 0; c < 4; c++) acc[r][c] += fa[r] * fb[c];
        }
        __syncthreads();
    }
    const float* a = (which == 0) ? g_ax : g_az;
    float* rowsq   = (which == 0) ? g_rowsqx : g_rowsqz;
    float ai[4], aj[4];
    #pragma unroll
    for (int r = 0; r < 4; r++) ai[r] = a[i0 + ty * 4 + r];
    #pragma unroll
    for (int c = 0; c < 4; c++) aj[c] = a[j0 + tx * 4 + c];
    if (t < 64) rowacc[t] = 0.0f;
    __syncthreads();
    float lsum = 0.0f;
    float lrow[4] = {0.f, 0.f, 0.f, 0.f};
    #pragma unroll
    for (int r = 0; r < 4; r++)
        #pragma unroll
        for (int c = 0; c < 4; c++) {
            float cv = fmaxf(ai[r] + aj[c] - 2.0f * acc[r][c], 0.0f);
            lsum += cv;
            lrow[r] += cv * cv;
        }
    #pragma unroll
    for (int r = 0; r < 4; r++) atomicAdd(&rowacc[ty * 4 + r], lrow[r]);
    float bs = blockReduce256(lsum, sh, t);
    if (t == 0) atomicAdd((which == 0) ? &g_sumCx : &g_sumCz, (double)bs);
    __syncthreads();
    if (t < 64) atomicAdd(&rowsq[i0 + t], rowacc[t]);
}

__global__ void k_scalars() {
    __shared__ float shx[256], shz[256];
    int t = threadIdx.x;
    float s1 = 0.0f, s2 = 0.0f;
    for (int i = t; i < Bn; i += 256) { s1 += g_rowsqx[i]; s2 += g_rowsqz[i]; }
    shx[t] = s1; shz[t] = s2;
    __syncthreads();
    for (int o = 128; o; o >>= 1) {
        if (t < o) { shx[t] += shx[t + o]; shz[t] += shz[t + o]; }
        __syncthreads();
    }
    if (t == 0) {
        float mx = (float)(g_sumCx / ((double)Bn * (double)Bn));
        float mz = (float)(g_sumCz / ((double)Bn * (double)Bn));
        float sx = 1.0f / (mx + 1e-8f);
        float sz = 1.0f / (mz + 1e-8f);
        g_sx = sx; g_sz = sz;
        g_mCx2 = sx * sx * shx[0] / ((float)Bn * (float)Bn);
        g_mCz2 = sz * sz * shz[0] / ((float)Bn * (float)Bn);
    }
}

__global__ void k_zb(const float* __restrict__ Z) {
    int idx = blockIdx.x * 256 + threadIdx.x;
    if (idx >= Bn * CQ) return;
    int i = idx / CQ, c = idx % CQ;
    float v = 0.0f;
    if (c < 64) v = Z[i * DZc + c];
    else if (c == 64) v = 1.0f;
    else if (c == 65) v = g_az[i];
    g_Zb[idx] = v;
}

__global__ void k_colsums(const float* __restrict__ X, const float* __restrict__ Z) {
    __shared__ float sh[8];
    int t = threadIdx.x;
    int r0 = blockIdx.x * 256;
    float s = 0.0f;
    for (int r = 0; r < 256; r++) s += X[(r0 + r) * DXc + t];
    atomicAdd(&g_xs[t], s);
    if (t < DZc) {
        float s2 = 0.0f;
        for (int r = 0; r < 256; r++) s2 += Z[(r0 + r) * DZc + t];
        atomicAdd(&g_zs[t], s2);
    }
    float a = g_ax[r0 + t];
    float b = g_az[r0 + t];
    float sa = blockReduce256(a, sh, t);
    if (t == 0) atomicAdd(&g_sax, sa);
    float sb = blockReduce256(b, sh, t);
    if (t == 0) atomicAdd(&g_saz, sb);
}

__global__ void k_pq2(const float* __restrict__ X, const float* __restrict__ Z) {
    int w = threadIdx.x >> 5, lane = threadIdx.x & 31;
    int i = blockIdx.x * 8 + w;
    float s = 0.0f;
    for (int k = lane; k < DXc; k += 32) s += X[i * DXc + k] * g_xs[k];
    #pragma unroll
    for (int o = 16; o; o >>= 1) s += __shfl_down_sync(0xffffffffu, s, o);
    float s2 = 0.0f;
    for (int k = lane; k < DZc; k += 32) s2 += Z[i * DZc + k] * g_zs[k];
    #pragma unroll
    for (int o = 16; o; o >>= 1) s2 += __shfl_down_sync(0xffffffffu, s2, o);
    if (lane == 0) {
        float sx = g_sx, sz = g_sz;
        g_p[i] = sx * ((float)Bn * g_ax[i] + g_sax - 2.0f * s);
        g_q[i] = sz * ((float)Bn * g_az[i] + g_saz - 2.0f * s2);
        g_cx[i] = sx * sx * g_rowsqx[i] * INV_B;
        g_cz[i] = sz * sz * g_rowsqz[i] * INV_B;
    }
}

__global__ void k_m1() {
    __shared__ float qs[Bn];
    __shared__ float czs[Bn];
    int t = threadIdx.x;
    for (int j = t; j < Bn; j += 256) { qs[j] = g_q[j]; czs[j] = g_cz[j]; }
    __syncthreads();
    int i = blockIdx.x * 256 + t;
    float pi2 = 2.0f * INV_B * g_p[i];
    float m = -1e30f;
    for (int j = 0; j < Bn; j++) m = fmaxf(m, pi2 * qs[j] - czs[j]);
    g_m[i] = m;
}

// iter-1 K build (rank-1 exponent, stabilized) + row-sum partials
__global__ void k_K1() {
    int tx = threadIdx.x, ty = threadIdx.y;
    int i0 = blockIdx.y * 64, j0 = blockIdx.x * 64;
    float pr[4], qc[4], czc[4], off[4];
    #pragma unroll
    for (int r = 0; r < 4; r++) {
        int i = i0 + ty * 4 + r;
        pr[r] = 2.0f * INV_B * g_p[i];
        off[r] = g_cx[i] + g_m[i];
    }
    #pragma unroll
    for (int c = 0; c < 4; c++) {
        int j = j0 + tx * 4 + c;
        qc[c] = g_q[j];
        czc[c] = g_cz[j];
    }
    float val[4][4];
    float rowp[4];
    #pragma unroll
    for (int r = 0; r < 4; r++) {
        rowp[r] = 0.0f;
        #pragma unroll
        for (int c = 0; c < 4; c++) {
            val[r][c] = __expf(pr[r] * qc[c] - czc[c] - off[r]);
            rowp[r] += val[r][c];
        }
    }
    #pragma unroll
    for (int r = 0; r < 4; r++) {
        #pragma unroll
        for (int o = 8; o; o >>= 1) rowp[r] += __shfl_xor_sync(0xffffffffu, rowp[r], o);
    }
    if (tx == 0) {
        #pragma unroll
        for (int r = 0; r < 4; r++) g_rsp[blockIdx.x][i0 + ty * 4 + r] = rowp[r];
    }
    #pragma unroll
    for (int r = 0; r < 4; r++) {
        float4 w = make_float4(val[r][0], val[r][1], val[r][2], val[r][3]);
        *(float4*)&g_K0[(size_t)(i0 + ty * 4 + r) * Bn + j0 + tx * 4] = w;
    }
    #pragma unroll
    for (int c = 0; c < 4; c++) {
        float4 w = make_float4(val[0][c], val[1][c], val[2][c], val[3][c]);
        *(float4*)&g_K0T[(size_t)(j0 + tx * 4 + c) * Bn + i0 + ty * 4] = w;
    }
}

__global__ void k_reg(const float* __restrict__ Z, const float* __restrict__ y) {
    __shared__ float zi[16][65];
    __shared__ float zj[128][65];
    __shared__ float yis[16], azis[16];
    __shared__ float sh[8];
    int t = threadIdx.x;
    int i0 = blockIdx.x * 16;
    float sz = g_sz;
    for (int idx = t; idx < 16 * 64; idx += 256) {
        int r = idx >> 6, k = idx & 63;
        zi[r][k] = Z[(i0 + r) * DZc + k];
    }
    if (t < 16) { yis[t] = y[i0 + t]; azis[t] = g_az[i0 + t]; }
    __syncthreads();
    int half = t >> 7;
    int jl = t & 127;
    float acc = 0.0f;
    for (int j0 = 0; j0 < Bn; j0 += 128) {
        __syncthreads();
        for (int idx = t; idx < 128 * 64; idx += 256) {
            int r = idx >> 6, k = idx & 63;
            zj[r][k] = Z[(j0 + r) * DZc + k];
        }
        __syncthreads();
        int j = j0 + jl;
        float azj = g_az[j];
        float yj = y[j];
        #pragma unroll
        for (int ii = 0; ii < 8; ii++) {
            int il = half * 8 + ii;
            int i = i0 + il;
            if (i == j) continue;
            float d = 0.0f;
            #pragma unroll 16
            for (int k = 0; k < 64; k++) d += zi[il][k] * zj[jl][k];
            float raw = azis[il] + azj - 2.0f * d;
            float Cz = sz * fmaxf(raw, 0.0f);
            float zd = fmaxf(Cz, 1e-4f);
            float df = __logf(fabsf(yis[il] - yj) + 1e-6f) - __logf(zd + 1e-6f);
            acc += df * df;
        }
    }
    float bs = blockReduce256(acc, sh, t);
    if (t == 0) atomicAdd(&g_reg, (double)bs);
}

// ------------- fused iteration kernel -------------
// mode 0: full iteration (A..E). mode 1: norm only (E). mode 2: A..C then stop.
__global__ void __launch_bounds__(NTH) k_iter(const float* __restrict__ X, int mode) {
    __shared__ SMU sm;
    int tid = threadIdx.x;
    int bid = blockIdx.x;
    int sense = *((volatile int*)&g_barSense);

    #define GRID_BAR() do {                                              \
        __syncthreads();                                                 \
        __threadfence();                                                 \
        if (tid == 0) {                                                  \
            int tgt = sense ^ 1;                                         \
            if (atomicAdd(&g_barCount, 1) == NBLK - 1) {                 \
                g_barCount = 0;                                          \
                __threadfence();                                         \
                *((volatile int*)&g_barSense) = tgt;                     \
            } else {                                                     \
                while (*((volatile int*)&g_barSense) != tgt) { __nanosleep(32); } \
            }                                                            \
        }                                                                \
        sense ^= 1;                                                      \
        __syncthreads();                                                 \
    } while (0)

    if (mode != 1) {
        // ---- Phase A: Yp[jp][i][c] = sum_{j in chunk jp} K0[i,j] * v_j * Zb[j,c]
        {
            int tx = tid & 15, ty = tid >> 4;   // tx: 5 cols each; ty: 4 rows each
            for (int tile = bid; tile < 128; tile += NBLK) {
                int i0 = (tile & 15) << 7;
                int jp = tile >> 4;
                int jbase = jp << 8;
                if (tid < 256) sm.a.vsh[tid] = g_v[jbase + tid];
                float acc[4][5];
                #pragma unroll
                for (int r = 0; r < 4; r++)
                    #pragma unroll
                    for (int q = 0; q < 5; q++) acc[r][q] = 0.0f;
                __syncthreads();
                for (int jc = 0; jc < 16; jc++) {
                    #pragma unroll
                    for (int e = 0; e < 4; e++) {
                        int idx = tid + e * 512;
                        int jj = idx & 15, row = idx >> 4;
                        sm.a.Ks[jj][row] = g_K0[(size_t)(i0 + row) * Bn + jbase + jc * 16 + jj];
                    }
                    for (int idx = tid; idx < 1280; idx += 512) {
                        int jj = idx / 80, c = idx % 80;
                        sm.a.Bs[jj][c] = sm.a.vsh[jc * 16 + jj] * g_Zb[(jbase + jc * 16 + jj) * CQ + c];
                    }
                    __syncthreads();
                    #pragma unroll
                    for (int jj = 0; jj < 16; jj++) {
                        float4 fa = *(const float4*)&sm.a.Ks[jj][ty * 4];
                        float a4[4] = {fa.x, fa.y, fa.z, fa.w};
                        float fb[5];
                        #pragma unroll
                        for (int q = 0; q < 5; q++) fb[q] = sm.a.Bs[jj][tx * 5 + q];
                        #pragma unroll
                        for (int r = 0; r < 4; r++)
                            #pragma unroll
                            for (int q = 0; q < 5; q++) acc[r][q] += a4[r] * fb[q];
                    }
                    __syncthreads();
                }
                #pragma unroll
                for (int r = 0; r < 4; r++)
                    #pragma unroll
                    for (int q = 0; q < 5; q++)
                        g_Yp[(size_t)jp * Bn * CQ + (size_t)(i0 + ty * 4 + r) * CQ + tx * 5 + q] = acc[r][q];
            }
        }
        GRID_BAR();
        // ---- Phase A2: Y = u * sum partials
        for (int idx = bid * NTH + tid; idx < Bn * CQ; idx += NBLK * NTH) {
            int i = idx / CQ;
            float s = 0.0f;
            #pragma unroll
            for (int p2 = 0; p2 < NJ; p2++) s += g_Yp[(size_t)p2 * Bn * CQ + idx];
            g_Y[idx] = g_u[i] * s;
        }
        GRID_BAR();
        // ---- Phase B: Pp[by][xc][c] = sum_{i in chunk by} X[i,xc]*Y[i,c]; bx==0: cs/as
        {
            int tx = tid & 15, ty = tid >> 4;  // ty 0..31
            for (int tile = bid; tile < 128; tile += NBLK) {
                int bx = tile & 15, by = tile >> 4;
                int xc0 = bx * 16, ibase = by * 256;
                float acc0 = 0.f, acc1 = 0.f, acc2 = 0.f, csl = 0.f, asl = 0.f;
                for (int ic = 0; ic < 16; ic++) {
                    if (tid < 256) {
                        int ii = tid >> 4, xcl = tid & 15;
                        sm.b.Xs[ii][xcl] = X[(ibase + ic * 16 + ii) * DXc + xc0 + xcl];
                    }
                    if (tid < 16) sm.b.axsh[tid] = g_ax[ibase + ic * 16 + tid];
                    for (int idx = tid; idx < 1280; idx += 512) {
                        int ii = idx / 80, c = idx % 80;
                        sm.b.Ms[ii][c] = g_Y[(ibase + ic * 16 + ii) * CQ + c];
                    }
                    __syncthreads();
                    #pragma unroll
                    for (int ii = 0; ii < 16; ii++) {
                        float fa = sm.b.Xs[ii][tx];
                        acc0 += fa * sm.b.Ms[ii][ty];
                        acc1 += fa * sm.b.Ms[ii][ty + 32];
                        if (ty < 16) acc2 += fa * sm.b.Ms[ii][ty + 64];
                    }
                    if (bx == 0 && tid < 80) {
                        #pragma unroll
                        for (int ii = 0; ii < 16; ii++) {
                            float mval = sm.b.Ms[ii][tid];
                            csl += mval;
                            asl += sm.b.axsh[ii] * mval;
                        }
                    }
                    __syncthreads();
                }
                size_t pb = (size_t)by * DXc * CQ + (size_t)(xc0 + tx) * CQ;
                g_Pp[pb + ty] = acc0;
                g_Pp[pb + ty + 32] = acc1;
                if (ty < 16) g_Pp[pb + ty + 64] = acc2;
                if (bx == 0 && tid < 80) { g_csp[by][tid] = csl; g_asp[by][tid] = asl; }
            }
        }
        GRID_BAR();
        // ---- Phase C: A[i,c] = sx*(ax_i*cs_c + as_c) - 2sx * sum_k X[i,k]*P[k,c]
        {
            int tx = tid & 15, ty = tid >> 4;  // tx: c; ty: 4 rows each
            for (int tile = bid; tile < 80; tile += NBLK) {
                int ct = tile % 5, it = tile / 5;
                int c0 = ct * 16, i0 = it * 128;
                if (tid < 16) {
                    float cs = 0.f, as = 0.f;
                    #pragma unroll
                    for (int p2 = 0; p2 < NI; p2++) { cs += g_csp[p2][c0 + tid]; as += g_asp[p2][c0 + tid]; }
                    sm.c.csRs[tid] = cs; sm.c.asRs[tid] = as;
                }
                float acc[4] = {0.f, 0.f, 0.f, 0.f};
                __syncthreads();
                for (int k0 = 0; k0 < DXc; k0 += 16) {
                    #pragma unroll
                    for (int e = 0; e < 4; e++) {
                        int idx = tid + e * 512;
                        int kk = idx & 15, row = idx >> 4;
                        sm.c.Xt[kk][row] = X[(i0 + row) * DXc + k0 + kk];
                    }
                    if (tid < 256) {
                        int kk = tid >> 4, cc = tid & 15;
                        float s = 0.0f;
                        #pragma unroll
                        for (int p2 = 0; p2 < NI; p2++)
                            s += g_Pp[(size_t)p2 * DXc * CQ + (size_t)(k0 + kk) * CQ + c0 + cc];
                        sm.c.Ps[kk][cc] = s;
                    }
                    __syncthreads();
                    #pragma unroll
                    for (int kk = 0; kk < 16; kk++) {
                        float4 fa = *(const float4*)&sm.c.Xt[kk][ty * 4];
                        float a4[4] = {fa.x, fa.y, fa.z, fa.w};
                        float b = sm.c.Ps[kk][tx];
                        #pragma unroll
                        for (int r = 0; r < 4; r++) acc[r] += a4[r] * b;
                    }
                    __syncthreads();
                }
                float sxv = g_sx;
                float csc = sm.c.csRs[tx], asc = sm.c.asRs[tx];
                #pragma unroll
                for (int r = 0; r < 4; r++) {
                    int i = i0 + ty * 4 + r;
                    g_A[i * CQ + c0 + tx] = sxv * (g_ax[i] * csc + asc) - 2.0f * sxv * acc[r];
                }
            }
        }
        if (mode == 2) return;
        GRID_BAR();
        // ---- Phase D: K0' = exp(...); also write K0T and row-sum partials
        {
            int tx = tid & 15, ty = tid >> 4;  // tx: 4 cols; ty: 2 rows each (64x64 tile)
            for (int tile = bid; tile < 1024; tile += NBLK) {
                int bx = tile & 31, by = tile >> 5;
                int i0 = by * 64, j0 = bx * 64;
                __syncthreads();
                #pragma unroll
                for (int e = 0; e < 2; e++) {
                    int idx = tid + e * 512;
                    int row = idx >> 4, q4 = idx & 15;
                    float4 f = *(const float4*)&g_A[(i0 + row) * CQ + q4 * 4];
                    sm.d.At[q4 * 4 + 0][row] = f.x;
                    sm.d.At[q4 * 4 + 1][row] = f.y;
                    sm.d.At[q4 * 4 + 2][row] = f.z;
                    sm.d.At[q4 * 4 + 3][row] = f.w;
                }
                #pragma unroll
                for (int e = 0; e < 2; e++) {
                    int idx = tid + e * 512;
                    int row = idx >> 4, q4 = idx & 15;
                    float4 f = *(const float4*)&g_Zb[(j0 + row) * CQ + q4 * 4];
                    sm.d.Zt[q4 * 4 + 0][row] = f.x;
                    sm.d.Zt[q4 * 4 + 1][row] = f.y;
                    sm.d.Zt[q4 * 4 + 2][row] = f.z;
                    sm.d.Zt[q4 * 4 + 3][row] = f.w;
                }
                if (tid < 64) {
                    sm.d.a0s[tid] = g_A[(i0 + tid) * CQ + 64];
                    sm.d.a1s[tid] = g_A[(i0 + tid) * CQ + 65];
                    sm.d.cxs[tid] = g_cx[i0 + tid];
                    sm.d.azs[tid] = g_az[j0 + tid];
                    sm.d.czs[tid] = g_cz[j0 + tid];
                }
                __syncthreads();
                float acc[2][4];
                #pragma unroll
                for (int r = 0; r < 2; r++)
                    #pragma unroll
                    for (int c = 0; c < 4; c++) acc[r][c] = 0.0f;
                #pragma unroll
                for (int k = 0; k < 64; k++) {
                    float2 fa = *(const float2*)&sm.d.At[k][ty * 2];
                    float4 fb = *(const float4*)&sm.d.Zt[k][tx * 4];
                    float a2[2] = {fa.x, fa.y};
                    float b4[4] = {fb.x, fb.y, fb.z, fb.w};
                    #pragma unroll
                    for (int r = 0; r < 2; r++)
                        #pragma unroll
                        for (int c = 0; c < 4; c++) acc[r][c] += a2[r] * b4[c];
                }
                float sz = g_sz;
                float val[2][4], rowp[2];
                #pragma unroll
                for (int r = 0; r < 2; r++) {
                    float al = 2.0f * sz * sm.d.a0s[ty * 2 + r];
                    float be = 2.0f * sz * sm.d.a1s[ty * 2 + r] - sm.d.cxs[ty * 2 + r];
                    rowp[r] = 0.0f;
                    #pragma unroll
                    for (int c = 0; c < 4; c++) {
                        val[r][c] = __expf(al * sm.d.azs[tx * 4 + c] + be - sm.d.czs[tx * 4 + c]
                                           - 4.0f * sz * acc[r][c]);
                        rowp[r] += val[r][c];
                    }
                }
                #pragma unroll
                for (int r = 0; r < 2; r++) {
                    #pragma unroll
                    for (int o = 8; o; o >>= 1) rowp[r] += __shfl_xor_sync(0xffffffffu, rowp[r], o);
                }
                if (tx == 0) {
                    g_rsp[bx][i0 + ty * 2 + 0] = rowp[0];
                    g_rsp[bx][i0 + ty * 2 + 1] = rowp[1];
                }
                #pragma unroll
                for (int r = 0; r < 2; r++) {
                    float4 w = make_float4(val[r][0], val[r][1], val[r][2], val[r][3]);
                    *(float4*)&g_K0[(size_t)(i0 + ty * 2 + r) * Bn + j0 + tx * 4] = w;
                }
                #pragma unroll
                for (int c = 0; c < 4; c++) {
                    float2 w = make_float2(val[0][c], val[1][c]);
                    *(float2*)&g_K0T[(size_t)(j0 + tx * 4 + c) * Bn + i0 + ty * 2] = w;
                }
            }
        }
        GRID_BAR();
    }

    // ---- Phase E: 5-round normalization; round-1 row pass from partials
    {
        int i = bid * NTH + tid;
        if (i < Bn) {
            float s = 0.0f;
            #pragma unroll
            for (int bx = 0; bx < 32; bx++) s += g_rsp[bx][i];
            g_u[i] = INV_B / (s + 1e-8f);
            g_v[i] = 1.0f;
        }
    }
    GRID_BAR();
    int grp = tid >> 7, lt = tid & 127;
    for (int p = 0; p < 9; p++) {
        bool isCol = ((p & 1) == 0);
        const float* M = isCol ? g_K0T : g_K0;
        const float* src = isCol ? g_u : g_v;
        float* dst = isCol ? g_v : g_u;
        for (int j = tid; j < Bn; j += NTH) sm.e.vs[j] = src[j];
        __syncthreads();
        for (int base = bid * 4; base < Bn; base += NBLK * 4) {
            int row = base + grp;
            const float4* r4 = (const float4*)&M[(size_t)row * Bn];
            const float4* v4 = (const float4*)sm.e.vs;
            float s = 0.0f;
            #pragma unroll
            for (int e = 0; e < 4; e++) {
                int q = lt + e * 128;
                float4 a = r4[q], b = v4[q];
                s += a.x * b.x + a.y * b.y + a.z * b.z + a.w * b.w;
            }
            #pragma unroll
            for (int o = 16; o; o >>= 1) s += __shfl_down_sync(0xffffffffu, s, o);
            if ((lt & 31) == 0) sm.e.red[grp][lt >> 5] = s;
            __syncthreads();
            if (lt == 0) {
                float tot = sm.e.red[grp][0] + sm.e.red[grp][1] + sm.e.red[grp][2] + sm.e.red[grp][3];
                float o = dst[row];
                dst[row] = o * INV_B / (o * tot + 1e-8f);
            }
            __syncthreads();
        }
        if (p < 8) GRID_BAR();
    }
    #undef GRID_BAR
}

// epilogue cross term (uses A from mode-2 pass + final u, v, K0)
__global__ void __launch_bounds__(256) k_cross() {
    __shared__ float At[64][68];
    __shared__ float Zt[64][68];
    __shared__ float a0s[64], a1s[64], azs[64], us[64];
    __shared__ float sh[8];
    int tx = threadIdx.x, ty = threadIdx.y;
    int t = ty * 16 + tx;
    int i0 = blockIdx.y * 64, j0 = blockIdx.x * 64;
    #pragma unroll
    for (int e = 0; e < 16; e++) {
        int idx = t + e * 256;
        int r = idx >> 6, k = idx & 63;
        At[k][r] = g_A[(i0 + r) * CQ + k];
        Zt[k][r] = g_Zb[(j0 + r) * CQ + k];
    }
    if (t < 64) {
        a0s[t] = g_A[(i0 + t) * CQ + 64];
        a1s[t] = g_A[(i0 + t) * CQ + 65];
        azs[t] = g_az[j0 + t];
        us[t]  = g_u[i0 + t];
    }
    __syncthreads();
    float acc[4][4];
    #pragma unroll
    for (int r = 0; r < 4; r++)
        #pragma unroll
        for (int c = 0; c < 4; c++) acc[r][c] = 0.0f;
    #pragma unroll
    for (int k = 0; k < 64; k++) {
        float4 fa = *(const float4*)&At[k][ty * 4];
        float4 fb = *(const float4*)&Zt[k][tx * 4];
        float a4[4] = {fa.x, fa.y, fa.z, fa.w};
        float b4[4] = {fb.x, fb.y, fb.z, fb.w};
        #pragma unroll
        for (int r = 0; r < 4; r++)
            #pragma unroll
            for (int c = 0; c < 4; c++) acc[r][c] += a4[r] * b4[c];
    }
    float sz = g_sz;
    float4 vj = *(const float4*)&g_v[j0 + tx * 4];
    float v4[4] = {vj.x, vj.y, vj.z, vj.w};
    float part = 0.0f;
    #pragma unroll
    for (int r = 0; r < 4; r++) {
        int i = i0 + ty * 4 + r;
        float ui = us[ty * 4 + r];
        float a0 = a0s[ty * 4 + r], a1 = a1s[ty * 4 + r];
        float4 k4 = *(const float4*)&g_K0[(size_t)i * Bn + j0 + tx * 4];
        float kk[4] = {k4.x, k4.y, k4.z, k4.w};
        #pragma unroll
        for (int c = 0; c < 4; c++) {
            float crossv = sz * (azs[tx * 4 + c] * a0 + a1 - 2.0f * acc[r][c]);
            part += crossv * ui * kk[c] * v4[c];
        }
    }
    float bs = blockReduce256(part, sh, t);
    if (t == 0) atomicAdd(&g_cross, (double)bs);
}

__global__ void k_final(float* out) {
    float gw = g_mCx2 + g_mCz2 - 2.0f * (float)g_cross;
    gw = fmaxf(gw, 0.0f);
    double denom = (double)Bn * (double)(Bn - 1);
    out[0] = gw + (float)(g_reg / denom);
}

// ------------- launch -------------
extern "C" void kernel_launch(void* const* d_in, const int* in_sizes, int n_in,
                              void* d_out, int out_size) {
    const float* x = (const float*)d_in[0];
    const float* z = (const float*)d_in[1];
    const float* y = (const float*)d_in[2];
    float* out = (float*)d_out;
    (void)in_sizes; (void)n_in; (void)out_size;

    dim3 t16(16, 16);
    dim3 g3232(32, 32);

    k_init<<<8, 256>>>();
    k_sqnorm<<<Bn, 256>>>(x, DXc, 0);
    k_sqnorm<<<Bn, 256>>>(z, DZc, 1);
    k_stats<<<g3232, t16>>>(x, DXc, 0);
    k_stats<<<g3232, t16>>>(z, DZc, 1);
    k_scalars<<<1, 256>>>();
    k_zb<<<(Bn * CQ + 255) / 256, 256>>>(z);
    k_colsums<<<8, 256>>>(x, z);
    k_reg<<<Bn / 16, 256>>>(z, y);
    k_pq2<<<Bn / 8, 256>>>(x, z);

    // iteration 1 (rank-1 exponent, stabilized) then norm-only fused kernel
    k_m1<<<8, 256>>>();
    k_K1<<<g3232, t16>>>();
    k_iter<<<NBLK, NTH>>>(x, 1);

    // iterations 2..50 fully fused
    for (int it = 1; it < 50; it++)
        k_iter<<<NBLK, NTH>>>(x, 0);

    // epilogue: recompute A for final T, then cross term
    k_iter<<<NBLK, NTH>>>(x, 2);
    k_cross<<<g3232, t16>>>();
    k_final<<<1, 1>>>(out);
}

// round 12
// speedup vs baseline: 1.0011x; 1.0011x over previous
#include <cuda_runtime.h>
#include <math.h>

#define Bn 2048
#define DXc 256
#define DZc 64
#define CQ 80
#define INV_B (1.0f/2048.0f)
#define NBLK 148
#define NTH 512
#define NJ 8
#define NI 8

// ------------- device scratch -------------
__device__ float g_K0 [Bn*(size_t)Bn];
__device__ float g_K0T[Bn*(size_t)Bn];
__device__ float g_Zb [Bn*CQ];
__device__ float g_Y  [Bn*CQ];
__device__ float g_Yp [NJ*Bn*CQ];
__device__ float g_Pp [NI*DXc*CQ];
__device__ float g_csp[NI][CQ], g_asp[NI][CQ];
__device__ float g_A  [Bn*CQ];
__device__ float g_rsp[32][Bn];
__device__ float g_u[Bn], g_v[Bn];
__device__ float g_ax[Bn], g_az[Bn];
__device__ float g_cx[Bn], g_cz[Bn];
__device__ float g_rowsqx[Bn], g_rowsqz[Bn];
__device__ float g_p[Bn], g_q[Bn], g_m[Bn];
__device__ float g_xs[DXc], g_zs[DZc];
__device__ float g_sax, g_saz;
__device__ double g_sumCx, g_sumCz, g_reg, g_cross;
__device__ float g_sx, g_sz, g_mCx2, g_mCz2;
__device__ int g_barCount, g_barSense;

// shared-memory union for the fused iteration kernel
struct SA { float Ks[16][136]; float Bs[16][80]; float vsh[256]; };
struct SB { float Xs[16][16]; float Ms[16][80]; float axsh[16]; };
struct SC { float Xt[16][136]; float Ps[16][16]; float csRs[16]; float asRs[16]; };
struct SD { float At[64][72]; float Zt[64][68]; float a0s[64], a1s[64], cxs[64], azs[64], czs[64]; };
struct SE { float vs[Bn]; float red[4][4]; };
union SMU { SA a; SB b; SC c; SD d; SE e; };

// ------------- helpers -------------
__device__ __forceinline__ float blockReduce256(float v, float* sh, int t) {
    #pragma unroll
    for (int o = 16; o; o >>= 1) v += __shfl_down_sync(0xffffffffu, v, o);
    if ((t & 31) == 0) sh[t >> 5] = v;
    __syncthreads();
    if (t < 32) {
        v = (t < 8) ? sh[t] : 0.0f;
        #pragma unroll
        for (int o = 4; o; o >>= 1) v += __shfl_down_sync(0xffffffffu, v, o);
    }
    __syncthreads();
    return v;
}

// ------------- prologue -------------
__global__ void k_init() {
    int t = blockIdx.x * blockDim.x + threadIdx.x;
    if (t == 0) { g_sumCx = 0.0; g_sumCz = 0.0; g_reg = 0.0; g_cross = 0.0;
                  g_sax = 0.0f; g_saz = 0.0f; }
    if (t < Bn) { g_rowsqx[t] = 0.0f; g_rowsqz[t] = 0.0f; }
    if (t < DXc) g_xs[t] = 0.0f;
    if (t < DZc) g_zs[t] = 0.0f;
}

__global__ void k_sqnorm(const float* __restrict__ X, int D, int which) {
    __shared__ float sh[8];
    int i = blockIdx.x;
    float s = 0.0f;
    for (int k = threadIdx.x; k < D; k += 256) { float x = X[i * D + k]; s += x * x; }
    s = blockReduce256(s, sh, threadIdx.x);
    if (threadIdx.x == 0) { if (which == 0) g_ax[i] = s; else g_az[i] = s; }
}

__global__ void k_stats(const float* __restrict__ X, int D, int which) {
    __shared__ float Xa[64][17];
    __shared__ float Xb[64][17];
    __shared__ float rowacc[64];
    __shared__ float sh[8];
    int tx = threadIdx.x, ty = threadIdx.y;
    int t = ty * 16 + tx;
    int i0 = blockIdx.y * 64, j0 = blockIdx.x * 64;
    float acc[4][4];
    #pragma unroll
    for (int r = 0; r < 4; r++)
        #pragma unroll
        for (int c = 0; c < 4; c++) acc[r][c] = 0.0f;
    for (int k0 = 0; k0 < D; k0 += 16) {
        #pragma unroll
        for (int e = 0; e < 4; e++) {
            int idx = t + e * 256;
            int r = idx >> 4, kk = idx & 15;
            Xa[r][kk] = X[(i0 + r) * D + k0 + kk];
            Xb[r][kk] = X[(j0 + r) * D + k0 + kk];
        }
        __syncthreads();
        #pragma unroll
        for (int kk = 0; kk < 16; kk++) {
            float fa[4], fb[4];
            #pragma unroll
            for (int r = 0; r < 4; r++) fa[r] = Xa[ty * 4 + r][kk];
            #pragma unroll
            for (int c = 0; c < 4; c++) fb[c] = Xb[tx * 4 + c][kk];
            #pragma unroll
            for (int r = 0; r < 4; r++)
                #pragma unroll
                for (int c = 0; c < 4; c++) acc[r][c] += fa[r] * fb[c];
        }
        __syncthreads();
    }
    const float* a = (which == 0) ? g_ax : g_az;
    float* rowsq   = (which == 0) ? g_rowsqx : g_rowsqz;
    float ai[4], aj[4];
    #pragma unroll
    for (int r = 0; r < 4; r++) ai[r] = a[i0 + ty * 4 + r];
    #pragma unroll
    for (int c = 0; c < 4; c++) aj[c] = a[j0 + tx * 4 + c];
    if (t < 64) rowacc[t] = 0.0f;
    __syncthreads();
    float lsum = 0.0f;
    float lrow[4] = {0.f, 0.f, 0.f, 0.f};
    #pragma unroll
    for (int r = 0; r < 4; r++)
        #pragma unroll
        for (int c = 0; c < 4; c++) {
            float cv = fmaxf(ai[r] + aj[c] - 2.0f * acc[r][c], 0.0f);
            lsum += cv;
            lrow[r] += cv * cv;
        }
    #pragma unroll
    for (int r = 0; r < 4; r++) atomicAdd(&rowacc[ty * 4 + r], lrow[r]);
    float bs = blockReduce256(lsum, sh, t);
    if (t == 0) atomicAdd((which == 0) ? &g_sumCx : &g_sumCz, (double)bs);
    __syncthreads();
    if (t < 64) atomicAdd(&rowsq[i0 + t], rowacc[t]);
}

__global__ void k_scalars() {
    __shared__ float shx[256], shz[256];
    int t = threadIdx.x;
    float s1 = 0.0f, s2 = 0.0f;
    for (int i = t; i < Bn; i += 256) { s1 += g_rowsqx[i]; s2 += g_rowsqz[i]; }
    shx[t] = s1; shz[t] = s2;
    __syncthreads();
    for (int o = 128; o; o >>= 1) {
        if (t < o) { shx[t] += shx[t + o]; shz[t] += shz[t + o]; }
        __syncthreads();
    }
    if (t == 0) {
        float mx = (float)(g_sumCx / ((double)Bn * (double)Bn));
        float mz = (float)(g_sumCz / ((double)Bn * (double)Bn));
        float sx = 1.0f / (mx + 1e-8f);
        float sz = 1.0f / (mz + 1e-8f);
        g_sx = sx; g_sz = sz;
        g_mCx2 = sx * sx * shx[0] / ((float)Bn * (float)Bn);
        g_mCz2 = sz * sz * shz[0] / ((float)Bn * (float)Bn);
    }
}

__global__ void k_zb(const float* __restrict__ Z) {
    int idx = blockIdx.x * 256 + threadIdx.x;
    if (idx >= Bn * CQ) return;
    int i = idx / CQ, c = idx % CQ;
    float v = 0.0f;
    if (c < 64) v = Z[i * DZc + c];
    else if (c == 64) v = 1.0f;
    else if (c == 65) v = g_az[i];
    g_Zb[idx] = v;
}

__global__ void k_colsums(const float* __restrict__ X, const float* __restrict__ Z) {
    __shared__ float sh[8];
    int t = threadIdx.x;
    int r0 = blockIdx.x * 256;
    float s = 0.0f;
    for (int r = 0; r < 256; r++) s += X[(r0 + r) * DXc + t];
    atomicAdd(&g_xs[t], s);
    if (t < DZc) {
        float s2 = 0.0f;
        for (int r = 0; r < 256; r++) s2 += Z[(r0 + r) * DZc + t];
        atomicAdd(&g_zs[t], s2);
    }
    float a = g_ax[r0 + t];
    float b = g_az[r0 + t];
    float sa = blockReduce256(a, sh, t);
    if (t == 0) atomicAdd(&g_sax, sa);
    float sb = blockReduce256(b, sh, t);
    if (t == 0) atomicAdd(&g_saz, sb);
}

__global__ void k_pq2(const float* __restrict__ X, const float* __restrict__ Z) {
    int w = threadIdx.x >> 5, lane = threadIdx.x & 31;
    int i = blockIdx.x * 8 + w;
    float s = 0.0f;
    for (int k = lane; k < DXc; k += 32) s += X[i * DXc + k] * g_xs[k];
    #pragma unroll
    for (int o = 16; o; o >>= 1) s += __shfl_down_sync(0xffffffffu, s, o);
    float s2 = 0.0f;
    for (int k = lane; k < DZc; k += 32) s2 += Z[i * DZc + k] * g_zs[k];
    #pragma unroll
    for (int o = 16; o; o >>= 1) s2 += __shfl_down_sync(0xffffffffu, s2, o);
    if (lane == 0) {
        float sx = g_sx, sz = g_sz;
        g_p[i] = sx * ((float)Bn * g_ax[i] + g_sax - 2.0f * s);
        g_q[i] = sz * ((float)Bn * g_az[i] + g_saz - 2.0f * s2);
        g_cx[i] = sx * sx * g_rowsqx[i] * INV_B;
        g_cz[i] = sz * sz * g_rowsqz[i] * INV_B;
    }
}

__global__ void k_m1() {
    __shared__ float qs[Bn];
    __shared__ float czs[Bn];
    int t = threadIdx.x;
    for (int j = t; j < Bn; j += 256) { qs[j] = g_q[j]; czs[j] = g_cz[j]; }
    __syncthreads();
    int i = blockIdx.x * 256 + t;
    float pi2 = 2.0f * INV_B * g_p[i];
    float m = -1e30f;
    for (int j = 0; j < Bn; j++) m = fmaxf(m, pi2 * qs[j] - czs[j]);
    g_m[i] = m;
}

// iter-1 K build (rank-1 exponent, stabilized) + row-sum partials
__global__ void k_K1() {
    int tx = threadIdx.x, ty = threadIdx.y;
    int i0 = blockIdx.y * 64, j0 = blockIdx.x * 64;
    float pr[4], qc[4], czc[4], off[4];
    #pragma unroll
    for (int r = 0; r < 4; r++) {
        int i = i0 + ty * 4 + r;
        pr[r] = 2.0f * INV_B * g_p[i];
        off[r] = g_cx[i] + g_m[i];
    }
    #pragma unroll
    for (int c = 0; c < 4; c++) {
        int j = j0 + tx * 4 + c;
        qc[c] = g_q[j];
        czc[c] = g_cz[j];
    }
    float val[4][4];
    float rowp[4];
    #pragma unroll
    for (int r = 0; r < 4; r++) {
        rowp[r] = 0.0f;
        #pragma unroll
        for (int c = 0; c < 4; c++) {
            val[r][c] = __expf(pr[r] * qc[c] - czc[c] - off[r]);
            rowp[r] += val[r][c];
        }
    }
    #pragma unroll
    for (int r = 0; r < 4; r++) {
        #pragma unroll
        for (int o = 8; o; o >>= 1) rowp[r] += __shfl_xor_sync(0xffffffffu, rowp[r], o);
    }
    if (tx == 0) {
        #pragma unroll
        for (int r = 0; r < 4; r++) g_rsp[blockIdx.x][i0 + ty * 4 + r] = rowp[r];
    }
    #pragma unroll
    for (int r = 0; r < 4; r++) {
        float4 w = make_float4(val[r][0], val[r][1], val[r][2], val[r][3]);
        *(float4*)&g_K0[(size_t)(i0 + ty * 4 + r) * Bn + j0 + tx * 4] = w;
    }
    #pragma unroll
    for (int c = 0; c < 4; c++) {
        float4 w = make_float4(val[0][c], val[1][c], val[2][c], val[3][c]);
        *(float4*)&g_K0T[(size_t)(j0 + tx * 4 + c) * Bn + i0 + ty * 4] = w;
    }
}

__global__ void k_reg(const float* __restrict__ Z, const float* __restrict__ y) {
    __shared__ float zi[16][65];
    __shared__ float zj[128][65];
    __shared__ float yis[16], azis[16];
    __shared__ float sh[8];
    int t = threadIdx.x;
    int i0 = blockIdx.x * 16;
    float sz = g_sz;
    for (int idx = t; idx < 16 * 64; idx += 256) {
        int r = idx >> 6, k = idx & 63;
        zi[r][k] = Z[(i0 + r) * DZc + k];
    }
    if (t < 16) { yis[t] = y[i0 + t]; azis[t] = g_az[i0 + t]; }
    __syncthreads();
    int half = t >> 7;
    int jl = t & 127;
    float acc = 0.0f;
    for (int j0 = 0; j0 < Bn; j0 += 128) {
        __syncthreads();
        for (int idx = t; idx < 128 * 64; idx += 256) {
            int r = idx >> 6, k = idx & 63;
            zj[r][k] = Z[(j0 + r) * DZc + k];
        }
        __syncthreads();
        int j = j0 + jl;
        float azj = g_az[j];
        float yj = y[j];
        #pragma unroll
        for (int ii = 0; ii < 8; ii++) {
            int il = half * 8 + ii;
            int i = i0 + il;
            if (i == j) continue;
            float d = 0.0f;
            #pragma unroll 16
            for (int k = 0; k < 64; k++) d += zi[il][k] * zj[jl][k];
            float raw = azis[il] + azj - 2.0f * d;
            float Cz = sz * fmaxf(raw, 0.0f);
            float zd = fmaxf(Cz, 1e-4f);
            float df = __logf(fabsf(yis[il] - yj) + 1e-6f) - __logf(zd + 1e-6f);
            acc += df * df;
        }
    }
    float bs = blockReduce256(acc, sh, t);
    if (t == 0) atomicAdd(&g_reg, (double)bs);
}

// ------------- fused iteration kernel -------------
// mode 0: full iteration (A..E). mode 1: norm only (E). mode 2: A..C then stop.
__global__ void __launch_bounds__(NTH) k_iter(const float* __restrict__ X, int mode) {
    __shared__ SMU sm;
    int tid = threadIdx.x;
    int bid = blockIdx.x;
    int sense = *((volatile int*)&g_barSense);

    #define GRID_BAR() do {                                              \
        __syncthreads();                                                 \
        __threadfence();                                                 \
        if (tid == 0) {                                                  \
            int tgt = sense ^ 1;                                         \
            if (atomicAdd(&g_barCount, 1) == NBLK - 1) {                 \
                g_barCount = 0;                                          \
                __threadfence();                                         \
                *((volatile int*)&g_barSense) = tgt;                     \
            } else {                                                     \
                while (*((volatile int*)&g_barSense) != tgt) { __nanosleep(32); } \
            }                                                            \
        }                                                                \
        sense ^= 1;                                                      \
        __syncthreads();                                                 \
    } while (0)

    if (mode != 1) {
        // ---- Phase A: Yp[jp][i][c] = sum_{j in chunk jp} K0[i,j] * v_j * Zb[j,c]
        {
            int tx = tid & 15, ty = tid >> 4;   // tx: 5 cols each; ty: 4 rows each
            for (int tile = bid; tile < 128; tile += NBLK) {
                int i0 = (tile & 15) << 7;
                int jp = tile >> 4;
                int jbase = jp << 8;
                if (tid < 256) sm.a.vsh[tid] = g_v[jbase + tid];
                float acc[4][5];
                #pragma unroll
                for (int r = 0; r < 4; r++)
                    #pragma unroll
                    for (int q = 0; q < 5; q++) acc[r][q] = 0.0f;
                __syncthreads();
                for (int jc = 0; jc < 16; jc++) {
                    #pragma unroll
                    for (int e = 0; e < 4; e++) {
                        int idx = tid + e * 512;
                        int jj = idx & 15, row = idx >> 4;
                        sm.a.Ks[jj][row] = g_K0[(size_t)(i0 + row) * Bn + jbase + jc * 16 + jj];
                    }
                    for (int idx = tid; idx < 1280; idx += 512) {
                        int jj = idx / 80, c = idx % 80;
                        sm.a.Bs[jj][c] = sm.a.vsh[jc * 16 + jj] * g_Zb[(jbase + jc * 16 + jj) * CQ + c];
                    }
                    __syncthreads();
                    #pragma unroll
                    for (int jj = 0; jj < 16; jj++) {
                        float4 fa = *(const float4*)&sm.a.Ks[jj][ty * 4];
                        float a4[4] = {fa.x, fa.y, fa.z, fa.w};
                        float fb[5];
                        #pragma unroll
                        for (int q = 0; q < 5; q++) fb[q] = sm.a.Bs[jj][tx * 5 + q];
                        #pragma unroll
                        for (int r = 0; r < 4; r++)
                            #pragma unroll
                            for (int q = 0; q < 5; q++) acc[r][q] += a4[r] * fb[q];
                    }
                    __syncthreads();
                }
                #pragma unroll
                for (int r = 0; r < 4; r++)
                    #pragma unroll
                    for (int q = 0; q < 5; q++)
                        g_Yp[(size_t)jp * Bn * CQ + (size_t)(i0 + ty * 4 + r) * CQ + tx * 5 + q] = acc[r][q];
            }
        }
        GRID_BAR();
        // ---- Phase A2: Y = u * sum partials
        for (int idx = bid * NTH + tid; idx < Bn * CQ; idx += NBLK * NTH) {
            int i = idx / CQ;
            float s = 0.0f;
            #pragma unroll
            for (int p2 = 0; p2 < NJ; p2++) s += g_Yp[(size_t)p2 * Bn * CQ + idx];
            g_Y[idx] = g_u[i] * s;
        }
        GRID_BAR();
        // ---- Phase B: Pp[by][xc][c] = sum_{i in chunk by} X[i,xc]*Y[i,c]; bx==0: cs/as
        {
            int tx = tid & 15, ty = tid >> 4;  // ty 0..31
            for (int tile = bid; tile < 128; tile += NBLK) {
                int bx = tile & 15, by = tile >> 4;
                int xc0 = bx * 16, ibase = by * 256;
                float acc0 = 0.f, acc1 = 0.f, acc2 = 0.f, csl = 0.f, asl = 0.f;
                for (int ic = 0; ic < 16; ic++) {
                    if (tid < 256) {
                        int ii = tid >> 4, xcl = tid & 15;
                        sm.b.Xs[ii][xcl] = X[(ibase + ic * 16 + ii) * DXc + xc0 + xcl];
                    }
                    if (tid < 16) sm.b.axsh[tid] = g_ax[ibase + ic * 16 + tid];
                    for (int idx = tid; idx < 1280; idx += 512) {
                        int ii = idx / 80, c = idx % 80;
                        sm.b.Ms[ii][c] = g_Y[(ibase + ic * 16 + ii) * CQ + c];
                    }
                    __syncthreads();
                    #pragma unroll
                    for (int ii = 0; ii < 16; ii++) {
                        float fa = sm.b.Xs[ii][tx];
                        acc0 += fa * sm.b.Ms[ii][ty];
                        acc1 += fa * sm.b.Ms[ii][ty + 32];
                        if (ty < 16) acc2 += fa * sm.b.Ms[ii][ty + 64];
                    }
                    if (bx == 0 && tid < 80) {
                        #pragma unroll
                        for (int ii = 0; ii < 16; ii++) {
                            float mval = sm.b.Ms[ii][tid];
                            csl += mval;
                            asl += sm.b.axsh[ii] * mval;
                        }
                    }
                    __syncthreads();
                }
                size_t pb = (size_t)by * DXc * CQ + (size_t)(xc0 + tx) * CQ;
                g_Pp[pb + ty] = acc0;
                g_Pp[pb + ty + 32] = acc1;
                if (ty < 16) g_Pp[pb + ty + 64] = acc2;
                if (bx == 0 && tid < 80) { g_csp[by][tid] = csl; g_asp[by][tid] = asl; }
            }
        }
        GRID_BAR();
        // ---- Phase C: A[i,c] = sx*(ax_i*cs_c + as_c) - 2sx * sum_k X[i,k]*P[k,c]
        {
            int tx = tid & 15, ty = tid >> 4;  // tx: c; ty: 4 rows each
            for (int tile = bid; tile < 80; tile += NBLK) {
                int ct = tile % 5, it = tile / 5;
                int c0 = ct * 16, i0 = it * 128;
                if (tid < 16) {
                    float cs = 0.f, as = 0.f;
                    #pragma unroll
                    for (int p2 = 0; p2 < NI; p2++) { cs += g_csp[p2][c0 + tid]; as += g_asp[p2][c0 + tid]; }
                    sm.c.csRs[tid] = cs; sm.c.asRs[tid] = as;
                }
                float acc[4] = {0.f, 0.f, 0.f, 0.f};
                __syncthreads();
                for (int k0 = 0; k0 < DXc; k0 += 16) {
                    #pragma unroll
                    for (int e = 0; e < 4; e++) {
                        int idx = tid + e * 512;
                        int kk = idx & 15, row = idx >> 4;
                        sm.c.Xt[kk][row] = X[(i0 + row) * DXc + k0 + kk];
                    }
                    if (tid < 256) {
                        int kk = tid >> 4, cc = tid & 15;
                        float s = 0.0f;
                        #pragma unroll
                        for (int p2 = 0; p2 < NI; p2++)
                            s += g_Pp[(size_t)p2 * DXc * CQ + (size_t)(k0 + kk) * CQ + c0 + cc];
                        sm.c.Ps[kk][cc] = s;
                    }
                    __syncthreads();
                    #pragma unroll
                    for (int kk = 0; kk < 16; kk++) {
                        float4 fa = *(const float4*)&sm.c.Xt[kk][ty * 4];
                        float a4[4] = {fa.x, fa.y, fa.z, fa.w};
                        float b = sm.c.Ps[kk][tx];
                        #pragma unroll
                        for (int r = 0; r < 4; r++) acc[r] += a4[r] * b;
                    }
                    __syncthreads();
                }
                float sxv = g_sx;
                float csc = sm.c.csRs[tx], asc = sm.c.asRs[tx];
                #pragma unroll
                for (int r = 0; r < 4; r++) {
                    int i = i0 + ty * 4 + r;
                    g_A[i * CQ + c0 + tx] = sxv * (g_ax[i] * csc + asc) - 2.0f * sxv * acc[r];
                }
            }
        }
        if (mode == 2) return;
        GRID_BAR();
        // ---- Phase D: K0' = exp(...); also write K0T and row-sum partials
        {
            int tx = tid & 15, ty = tid >> 4;  // tx: 4 cols; ty: 2 rows each (64x64 tile)
            for (int tile = bid; tile < 1024; tile += NBLK) {
                int bx = tile & 31, by = tile >> 5;
                int i0 = by * 64, j0 = bx * 64;
                __syncthreads();
                #pragma unroll
                for (int e = 0; e < 2; e++) {
                    int idx = tid + e * 512;
                    int row = idx >> 4, q4 = idx & 15;
                    float4 f = *(const float4*)&g_A[(i0 + row) * CQ + q4 * 4];
                    sm.d.At[q4 * 4 + 0][row] = f.x;
                    sm.d.At[q4 * 4 + 1][row] = f.y;
                    sm.d.At[q4 * 4 + 2][row] = f.z;
                    sm.d.At[q4 * 4 + 3][row] = f.w;
                }
                #pragma unroll
                for (int e = 0; e < 2; e++) {
                    int idx = tid + e * 512;
                    int row = idx >> 4, q4 = idx & 15;
                    float4 f = *(const float4*)&g_Zb[(j0 + row) * CQ + q4 * 4];
                    sm.d.Zt[q4 * 4 + 0][row] = f.x;
                    sm.d.Zt[q4 * 4 + 1][row] = f.y;
                    sm.d.Zt[q4 * 4 + 2][row] = f.z;
                    sm.d.Zt[q4 * 4 + 3][row] = f.w;
                }
                if (tid < 64) {
                    sm.d.a0s[tid] = g_A[(i0 + tid) * CQ + 64];
                    sm.d.a1s[tid] = g_A[(i0 + tid) * CQ + 65];
                    sm.d.cxs[tid] = g_cx[i0 + tid];
                    sm.d.azs[tid] = g_az[j0 + tid];
                    sm.d.czs[tid] = g_cz[j0 + tid];
                }
                __syncthreads();
                float acc[2][4];
                #pragma unroll
                for (int r = 0; r < 2; r++)
                    #pragma unroll
                    for (int c = 0; c < 4; c++) acc[r][c] = 0.0f;
                #pragma unroll
                for (int k = 0; k < 64; k++) {
                    float2 fa = *(const float2*)&sm.d.At[k][ty * 2];
                    float4 fb = *(const float4*)&sm.d.Zt[k][tx * 4];
                    float a2[2] = {fa.x, fa.y};
                    float b4[4] = {fb.x, fb.y, fb.z, fb.w};
                    #pragma unroll
                    for (int r = 0; r < 2; r++)
                        #pragma unroll
                        for (int c = 0; c < 4; c++) acc[r][c] += a2[r] * b4[c];
                }
                float sz = g_sz;
                float val[2][4], rowp[2];
                #pragma unroll
                for (int r = 0; r < 2; r++) {
                    float al = 2.0f * sz * sm.d.a0s[ty * 2 + r];
                    float be = 2.0f * sz * sm.d.a1s[ty * 2 + r] - sm.d.cxs[ty * 2 + r];
                    rowp[r] = 0.0f;
                    #pragma unroll
                    for (int c = 0; c < 4; c++) {
                        val[r][c] = __expf(al * sm.d.azs[tx * 4 + c] + be - sm.d.czs[tx * 4 + c]
                                           - 4.0f * sz * acc[r][c]);
                        rowp[r] += val[r][c];
                    }
                }
                #pragma unroll
                for (int r = 0; r < 2; r++) {
                    #pragma unroll
                    for (int o = 8; o; o >>= 1) rowp[r] += __shfl_xor_sync(0xffffffffu, rowp[r], o);
                }
                if (tx == 0) {
                    g_rsp[bx][i0 + ty * 2 + 0] = rowp[0];
                    g_rsp[bx][i0 + ty * 2 + 1] = rowp[1];
                }
                #pragma unroll
                for (int r = 0; r < 2; r++) {
                    float4 w = make_float4(val[r][0], val[r][1], val[r][2], val[r][3]);
                    *(float4*)&g_K0[(size_t)(i0 + ty * 2 + r) * Bn + j0 + tx * 4] = w;
                }
                #pragma unroll
                for (int c = 0; c < 4; c++) {
                    float2 w = make_float2(val[0][c], val[1][c]);
                    *(float2*)&g_K0T[(size_t)(j0 + tx * 4 + c) * Bn + i0 + ty * 2] = w;
                }
            }
        }
        GRID_BAR();
    }

    // ---- Phase E: 5-round normalization; round-1 row pass from partials
    {
        int i = bid * NTH + tid;
        if (i < Bn) {
            float s = 0.0f;
            #pragma unroll
            for (int bx = 0; bx < 32; bx++) s += g_rsp[bx][i];
            g_u[i] = INV_B / (s + 1e-8f);
            g_v[i] = 1.0f;
        }
    }
    GRID_BAR();
    int grp = tid >> 7, lt = tid & 127;
    for (int p = 0; p < 9; p++) {
        bool isCol = ((p & 1) == 0);
        const float* M = isCol ? g_K0T : g_K0;
        const float* src = isCol ? g_u : g_v;
        float* dst = isCol ? g_v : g_u;
        for (int j = tid; j < Bn; j += NTH) sm.e.vs[j] = src[j];
        __syncthreads();
        for (int base = bid * 4; base < Bn; base += NBLK * 4) {
            int row = base + grp;
            const float4* r4 = (const float4*)&M[(size_t)row * Bn];
            const float4* v4 = (const float4*)sm.e.vs;
            float s = 0.0f;
            #pragma unroll
            for (int e = 0; e < 4; e++) {
                int q = lt + e * 128;
                float4 a = r4[q], b = v4[q];
                s += a.x * b.x + a.y * b.y + a.z * b.z + a.w * b.w;
            }
            #pragma unroll
            for (int o = 16; o; o >>= 1) s += __shfl_down_sync(0xffffffffu, s, o);
            if ((lt & 31) == 0) sm.e.red[grp][lt >> 5] = s;
            __syncthreads();
            if (lt == 0) {
                float tot = sm.e.red[grp][0] + sm.e.red[grp][1] + sm.e.red[grp][2] + sm.e.red[grp][3];
                float o = dst[row];
                dst[row] = o * INV_B / (o * tot + 1e-8f);
            }
            __syncthreads();
        }
        if (p < 8) GRID_BAR();
    }
    #undef GRID_BAR
}

// epilogue cross term (uses A from mode-2 pass + final u, v, K0)
__global__ void __launch_bounds__(256) k_cross() {
    __shared__ float At[64][68];
    __shared__ float Zt[64][68];
    __shared__ float a0s[64], a1s[64], azs[64], us[64];
    __shared__ float sh[8];
    int tx = threadIdx.x, ty = threadIdx.y;
    int t = ty * 16 + tx;
    int i0 = blockIdx.y * 64, j0 = blockIdx.x * 64;
    #pragma unroll
    for (int e = 0; e < 16; e++) {
        int idx = t + e * 256;
        int r = idx >> 6, k = idx & 63;
        At[k][r] = g_A[(i0 + r) * CQ + k];
        Zt[k][r] = g_Zb[(j0 + r) * CQ + k];
    }
    if (t < 64) {
        a0s[t] = g_A[(i0 + t) * CQ + 64];
        a1s[t] = g_A[(i0 + t) * CQ + 65];
        azs[t] = g_az[j0 + t];
        us[t]  = g_u[i0 + t];
    }
    __syncthreads();
    float acc[4][4];
    #pragma unroll
    for (int r = 0; r < 4; r++)
        #pragma unroll
        for (int c = 0; c < 4; c++) acc[r][c] = 0.0f;
    #pragma unroll
    for (int k = 0; k < 64; k++) {
        float4 fa = *(const float4*)&At[k][ty * 4];
        float4 fb = *(const float4*)&Zt[k][tx * 4];
        float a4[4] = {fa.x, fa.y, fa.z, fa.w};
        float b4[4] = {fb.x, fb.y, fb.z, fb.w};
        #pragma unroll
        for (int r = 0; r < 4; r++)
            #pragma unroll
            for (int c = 0; c < 4; c++) acc[r][c] += a4[r] * b4[c];
    }
    float sz = g_sz;
    float4 vj = *(const float4*)&g_v[j0 + tx * 4];
    float v4[4] = {vj.x, vj.y, vj.z, vj.w};
    float part = 0.0f;
    #pragma unroll
    for (int r = 0; r < 4; r++) {
        int i = i0 + ty * 4 + r;
        float ui = us[ty * 4 + r];
        float a0 = a0s[ty * 4 + r], a1 = a1s[ty * 4 + r];
        float4 k4 = *(const float4*)&g_K0[(size_t)i * Bn + j0 + tx * 4];
        float kk[4] = {k4.x, k4.y, k4.z, k4.w};
        #pragma unroll
        for (int c = 0; c < 4; c++) {
            float crossv = sz * (azs[tx * 4 + c] * a0 + a1 - 2.0f * acc[r][c]);
            part += crossv * ui * kk[c] * v4[c];
        }
    }
    float bs = blockReduce256(part, sh, t);
    if (t == 0) atomicAdd(&g_cross, (double)bs);
}

__global__ void k_final(float* out) {
    float gw = g_mCx2 + g_mCz2 - 2.0f * (float)g_cross;
    gw = fmaxf(gw, 0.0f);
    double denom = (double)Bn * (double)(Bn - 1);
    out[0] = gw + (float)(g_reg / denom);
}

// ------------- launch -------------
extern "C" void kernel_launch(void* const* d_in, const int* in_sizes, int n_in,
                              void* d_out, int out_size) {
    const float* x = (const float*)d_in[0];
    const float* z = (const float*)d_in[1];
    const float* y = (const float*)d_in[2];
    float* out = (float*)d_out;
    (void)in_sizes; (void)n_in; (void)out_size;

    dim3 t16(16, 16);
    dim3 g3232(32, 32);

    k_init<<<8, 256>>>();
    k_sqnorm<<<Bn, 256>>>(x, DXc, 0);
    k_sqnorm<<<Bn, 256>>>(z, DZc, 1);
    k_stats<<<g3232, t16>>>(x, DXc, 0);
    k_stats<<<g3232, t16>>>(z, DZc, 1);
    k_scalars<<<1, 256>>>();
    k_zb<<<(Bn * CQ + 255) / 256, 256>>>(z);
    k_colsums<<<8, 256>>>(x, z);
    k_reg<<<Bn / 16, 256>>>(z, y);
    k_pq2<<<Bn / 8, 256>>>(x, z);

    // iteration 1 (rank-1 exponent, stabilized) then norm-only fused kernel
    k_m1<<<8, 256>>>();
    k_K1<<<g3232, t16>>>();
    k_iter<<<NBLK, NTH>>>(x, 1);

    // iterations 2..50 fully fused
    for (int it = 1; it < 50; it++)
        k_iter<<<NBLK, NTH>>>(x, 0);

    // epilogue: recompute A for final T, then cross term
    k_iter<<<NBLK, NTH>>>(x, 2);
    k_cross<<<g3232, t16>>>();
    k_final<<<1, 1>>>(out);
}